// round 7
// baseline (speedup 1.0000x reference)
#include <cuda_runtime.h>
#include <cuda_fp16.h>
#include <cstdint>

#define Bb 48
#define Nn_ 96
#define Ee 1024
#define Dd 300
#define G3 900
#define G3P 904                          // padded to 113*8 for uint4 loads
#define Ll 4
#define NCc 7
#define BN_ (Bb * Nn_)                   // 4608
#define IN_DIM (Dd * (2 * Ll + 1) + Ee)  // 3724

// ---------------- scratch (static device arrays; no allocation) ----------------
__device__ float d_H0[BN_ * Dd];
__device__ float d_CL[Ll][BN_ * Dd];
__device__ float d_Pl[Ll][BN_ * Dd];
__device__ float d_GIc[BN_ * G3];
__device__ float d_GHp[BN_ * G3];
__device__ float d_GHc[BN_ * G3];
__device__ float d_Mall[BN_ * Dd];
__device__ float d_qdot[BN_];
__device__ __half d_pwiTh[Ll * Dd * G3P];  // k-major fp16 padded: [l][k][r<904]
__device__ __half d_pwhTh[Ll * Dd * G3P];
__device__ float d_Hcat[(size_t)BN_ * IN_DIM];
__device__ float d_x1[BN_ * Dd];
__device__ float d_x2[BN_ * Dd];

__device__ __forceinline__ float sigf(float x) { return 1.f / (1.f + expf(-x)); }

// ---- transpose+convert+pad: (L,900,300) fp32 -> (L,300,904) fp16, zeros in pad ----
__global__ void transpose_weights(const float* __restrict__ wih,
                                  const float* __restrict__ whh,
                                  __half* __restrict__ wihT,
                                  __half* __restrict__ whhT) {
    int idx = blockIdx.x * blockDim.x + threadIdx.x;
    if (idx >= Ll * Dd * G3P) return;
    int l = idx / (Dd * G3P);
    int rem = idx % (Dd * G3P);
    int k = rem / G3P;
    int r = rem % G3P;
    float vi = 0.f, vh = 0.f;
    if (r < G3) {
        size_t src = ((size_t)l * G3 + r) * Dd + k;
        vi = wih[src];
        vh = whh[src];
    }
    wihT[idx] = __float2half(vi);
    whhT[idx] = __float2half(vh);
}

// ================= 3xTF32 tensor-core GEMM (fp32-accurate) =================
// C(M,N) = A(M,K) @ op(B) + bias; op(B)=B(K,N) if !TRANSB else B(N,K)^T
// Block tile 128x64x16; 8 warps as 4(M) x 2(N); warp tile 32x32 via m16n8k8.
// Each operand split hi+lo; D += Ah*Bh + Ah*Bl + Al*Bh  (error ~2^-22).
#define GT_BM 128
#define GT_BN 64
#define GT_BK 16
#define GT_BMP 133  // As row pad (odd mod-32 stride: conflict-free)
#define GT_BNP 69   // Bs row pad

__device__ __forceinline__ uint32_t f2tf(float f) {
    uint32_t r;
    asm("cvt.rna.tf32.f32 %0, %1;" : "=r"(r) : "f"(f));
    return r;
}

__device__ __forceinline__ void split_tf32(float f, uint32_t& hi, uint32_t& lo) {
    hi = f2tf(f);
    lo = f2tf(f - __uint_as_float(hi));
}

__device__ __forceinline__ void mma_tf32(float* c, const uint32_t* a, uint32_t b0,
                                         uint32_t b1) {
    asm("mma.sync.aligned.m16n8k8.row.col.f32.tf32.tf32.f32 "
        "{%0,%1,%2,%3}, {%4,%5,%6,%7}, {%8,%9}, {%0,%1,%2,%3};"
        : "+f"(c[0]), "+f"(c[1]), "+f"(c[2]), "+f"(c[3])
        : "r"(a[0]), "r"(a[1]), "r"(a[2]), "r"(a[3]), "r"(b0), "r"(b1));
}

template <bool TRANSB, int ACT>
__global__ void __launch_bounds__(256, 2)
gemm_tc(const float* __restrict__ A, const float* __restrict__ Bm,
        const float* __restrict__ bias, float* __restrict__ C,
        int M, int Nc, int K) {
    __shared__ float As[GT_BK][GT_BMP];  // k-major
    __shared__ float Bs[GT_BK][GT_BNP];  // k-major
    int tid = threadIdx.x;  // 256
    int bm = blockIdx.y * GT_BM;
    int bn = blockIdx.x * GT_BN;
    int wid = tid >> 5;
    int lane = tid & 31;
    int warpM = wid >> 1;  // 0..3
    int warpN = wid & 1;   // 0..1
    int l4 = lane & 3;
    int g = lane >> 2;

    float acc[2][4][4] = {};  // [mf][nf][reg]

    for (int k0 = 0; k0 < K; k0 += GT_BK) {
        // stage A: As[k][m] = A[bm+m][k0+k]
#pragma unroll
        for (int e = tid; e < GT_BM * GT_BK; e += 256) {
            int r = e >> 4, c = e & 15;
            int gm = bm + r, gk = k0 + c;
            As[c][r] = (gm < M && gk < K) ? A[(size_t)gm * K + gk] : 0.f;
        }
        // stage B: Bs[k][n] = op(B)[k0+k][bn+n]
#pragma unroll
        for (int e = tid; e < GT_BN * GT_BK; e += 256) {
            if (TRANSB) {
                int n = e >> 4, c = e & 15;
                int gn = bn + n, gk = k0 + c;
                Bs[c][n] = (gn < Nc && gk < K) ? Bm[(size_t)gn * K + gk] : 0.f;
            } else {
                int c = e >> 6, n = e & 63;
                int gk = k0 + c, gn = bn + n;
                Bs[c][n] = (gk < K && gn < Nc) ? Bm[(size_t)gk * Nc + gn] : 0.f;
            }
        }
        __syncthreads();
#pragma unroll
        for (int kc = 0; kc < 2; kc++) {
            int kb = kc * 8;
            // A fragments: a0=(g,l4) a1=(g+8,l4) a2=(g,l4+4) a3=(g+8,l4+4)
            uint32_t ah[2][4], al[2][4];
#pragma unroll
            for (int mf = 0; mf < 2; mf++) {
                int mb = warpM * 32 + mf * 16;
                split_tf32(As[kb + l4][mb + g], ah[mf][0], al[mf][0]);
                split_tf32(As[kb + l4][mb + g + 8], ah[mf][1], al[mf][1]);
                split_tf32(As[kb + l4 + 4][mb + g], ah[mf][2], al[mf][2]);
                split_tf32(As[kb + l4 + 4][mb + g + 8], ah[mf][3], al[mf][3]);
            }
#pragma unroll
            for (int nf = 0; nf < 4; nf++) {
                int nb = warpN * 32 + nf * 8;
                uint32_t bh0, bl0, bh1, bl1;
                split_tf32(Bs[kb + l4][nb + g], bh0, bl0);
                split_tf32(Bs[kb + l4 + 4][nb + g], bh1, bl1);
#pragma unroll
                for (int mf = 0; mf < 2; mf++) {
                    mma_tf32(acc[mf][nf], al[mf], bh0, bh1);  // Al*Bh
                    mma_tf32(acc[mf][nf], ah[mf], bl0, bl1);  // Ah*Bl
                    mma_tf32(acc[mf][nf], ah[mf], bh0, bh1);  // Ah*Bh
                }
            }
        }
        __syncthreads();
    }

    // epilogue: c0:(g,2*l4) c1:(g,2*l4+1) c2:(g+8,2*l4) c3:(g+8,2*l4+1)
#pragma unroll
    for (int mf = 0; mf < 2; mf++) {
#pragma unroll
        for (int nf = 0; nf < 4; nf++) {
            int gm0 = bm + warpM * 32 + mf * 16 + g;
            int gn0 = bn + warpN * 32 + nf * 8 + 2 * l4;
#pragma unroll
            for (int hi = 0; hi < 2; hi++) {
                int gm = gm0 + hi * 8;
                if (gm >= M) continue;
#pragma unroll
                for (int jj = 0; jj < 2; jj++) {
                    int gn = gn0 + jj;
                    if (gn >= Nc) continue;
                    float v = acc[mf][nf][hi * 2 + jj] + bias[gn];
                    if (ACT == 1) v = fmaxf(v, 0.f);
                    C[(size_t)gm * Nc + gn] = v;
                }
            }
        }
    }
}

// ---------------- qdot[b,i] = Cin[b,i,:] . wq ----------------
__global__ void qdot_kernel(const float* __restrict__ Cin, const float* __restrict__ wq,
                            float* __restrict__ qdot) {
    int row = blockIdx.x * (blockDim.x / 32) + (threadIdx.x / 32);
    int lane = threadIdx.x & 31;
    if (row >= BN_) return;
    float s = 0.f;
    for (int k = lane; k < Dd; k += 32) s += Cin[(size_t)row * Dd + k] * wq[k];
#pragma unroll
    for (int o = 16; o; o >>= 1) s += __shfl_down_sync(0xffffffffu, s, o);
    if (lane == 0) qdot[row] = s;
}

// ================ persistent per-batch scan ================
// grid = 48 (one block per batch), block = 256 threads.
#define SCAN_SMEM_FLOATS (Nn_ * Dd + 304 + G3P + Nn_ + Nn_ + 256 + G3P)
#define SCAN_SMEM_BYTES (SCAN_SMEM_FLOATS * 4)

// gi[r] = sum_k Ms[k]*W[k][r] + bias[r], W fp16 k-major padded to 904.
// Split-K: threads 0..112 k in [0,150), threads 113..225 k in [150,300).
// Each thread owns 8 rows via one LDG.128 per k. Called by ALL 256 threads.
__device__ __forceinline__ void matvec_900h(const __half* __restrict__ W,
                                            const float* __restrict__ bias,
                                            const float* __restrict__ Ms,
                                            float* __restrict__ gi,
                                            float* __restrict__ part, int t) {
    float a0 = 0.f, a1 = 0.f, a2 = 0.f, a3 = 0.f;
    float a4 = 0.f, a5 = 0.f, a6 = 0.f, a7 = 0.f;
    int rg = 0;
    if (t < 226) {
        rg = (t < 113) ? t : (t - 113);
        int k0 = (t < 113) ? 0 : 150;
        const uint4* wp = (const uint4*)W;  // 113 uint4 per k-row (904 halves)
#pragma unroll 2
        for (int k = k0; k < k0 + 150; k++) {
            float m = Ms[k];
            uint4 wv = wp[(size_t)k * 113 + rg];
            float2 f0 = __half22float2(*reinterpret_cast<const __half2*>(&wv.x));
            float2 f1 = __half22float2(*reinterpret_cast<const __half2*>(&wv.y));
            float2 f2 = __half22float2(*reinterpret_cast<const __half2*>(&wv.z));
            float2 f3 = __half22float2(*reinterpret_cast<const __half2*>(&wv.w));
            a0 += m * f0.x; a1 += m * f0.y;
            a2 += m * f1.x; a3 += m * f1.y;
            a4 += m * f2.x; a5 += m * f2.y;
            a6 += m * f3.x; a7 += m * f3.y;
        }
    }
    if (t >= 113 && t < 226) {
        int r = rg * 8;
        part[r + 0] = a0; part[r + 1] = a1; part[r + 2] = a2; part[r + 3] = a3;
        part[r + 4] = a4; part[r + 5] = a5; part[r + 6] = a6; part[r + 7] = a7;
    }
    __syncthreads();
    if (t < 113) {
        int r = rg * 8;
        float v[8] = {a0, a1, a2, a3, a4, a5, a6, a7};
#pragma unroll
        for (int j = 0; j < 8; j++) {
            int rr = r + j;
            if (rr < G3) gi[rr] = v[j] + part[rr] + bias[rr];
        }
    }
    __syncthreads();
}

__global__ void __launch_bounds__(256, 1)
scan_layer(const float* __restrict__ Cin, const float* __restrict__ Hin,
           const float* __restrict__ GHp, const float* __restrict__ qdot,
           const float* __restrict__ adj, const __half* __restrict__ Wi,
           const __half* __restrict__ Wh, const float* __restrict__ pbi,
           const float* __restrict__ pbh, const float* __restrict__ wk,
           const float* __restrict__ gbp, float* __restrict__ Pout,
           float* __restrict__ Mall) {
    extern __shared__ float sm[];
    float* Ps = sm;             // 96*300
    float* Ms = Ps + Nn_ * Dd;  // 304
    float* gi = Ms + 304;       // 904
    float* wsm = gi + G3P;      // 96
    float* kap = wsm + Nn_;     // 96
    float* red = kap + Nn_;     // 256
    float* part = red + 256;    // 904

    int b = blockIdx.x;
    int t = threadIdx.x;
    float gb = gbp[0];

    // ---- step 0: p0 = GRU(x=0, h=Cin[b,0,:]) ----
    for (int d = t; d < Dd; d += 256) Ms[d] = Cin[((size_t)b * Nn_) * Dd + d];
    __syncthreads();
    matvec_900h(Wh, pbh, Ms, gi, part, t);  // gh = h @ pwh^T + pbh
    {
        float kp = 0.f;
        for (int d = t; d < Dd; d += 256) {
            float r_ = sigf(pbi[d] + gi[d]);
            float z = sigf(pbi[Dd + d] + gi[Dd + d]);
            float n_ = tanhf(pbi[2 * Dd + d] + r_ * gi[2 * Dd + d]);
            float h = Ms[d];
            float p = (1.f - z) * n_ + z * h;
            Ps[d] = p;
            Pout[((size_t)b * Nn_) * Dd + d] = p;
            Mall[((size_t)b * Nn_) * Dd + d] = 0.f;
            kp += p * wk[d];
        }
        red[t] = kp;
        __syncthreads();
        for (int s = 128; s; s >>= 1) {
            if (t < s) red[t] += red[t + s];
            __syncthreads();
        }
        if (t == 0) kap[0] = red[0];
        __syncthreads();
    }

    // ---- steps 1..95 ----
    for (int i = 1; i < Nn_; i++) {
        float qd = qdot[b * Nn_ + i];
        float aval = -1e30f;
        if (t < i) {
            float m = adj[((size_t)b * Nn_ + i) * Nn_ + t];
            if (m != 0.f) aval = qd + kap[t] + gb;
        }
        red[t] = aval;
        __syncthreads();
        for (int s = 128; s; s >>= 1) {
            if (t < s) red[t] = fmaxf(red[t], red[t + s]);
            __syncthreads();
        }
        float mx = red[0];
        __syncthreads();
        float e = (aval > -1e29f) ? __expf(aval - mx) : 0.f;
        red[t] = e;
        __syncthreads();
        for (int s = 128; s; s >>= 1) {
            if (t < s) red[t] += red[t + s];
            __syncthreads();
        }
        float inv = 1.f / red[0];
        __syncthreads();
        if (t < Nn_) wsm[t] = e * inv;
        __syncthreads();

        // M = sum_j w_j * P_j (SMEM-resident P)
        for (int d = t; d < Dd; d += 256) {
            float m = 0.f;
            for (int j = 0; j < i; j++) m += wsm[j] * Ps[j * Dd + d];
            Ms[d] = m;
            Mall[((size_t)b * Nn_ + i) * Dd + d] = m;
        }
        __syncthreads();

        // gi = M @ pwi^T + pbi (fp16 split-K matvec)
        matvec_900h(Wi, pbi, Ms, gi, part, t);

        // p_i = GRU(gi, GHp row, h = Hin row); write P; kappa_i
        {
            const float* ghrow = GHp + ((size_t)b * Nn_ + i) * G3;
            const float* hrow = Hin + ((size_t)b * Nn_ + i) * Dd;
            float kp = 0.f;
            for (int d = t; d < Dd; d += 256) {
                float r_ = sigf(gi[d] + ghrow[d]);
                float z = sigf(gi[Dd + d] + ghrow[Dd + d]);
                float n_ = tanhf(gi[2 * Dd + d] + r_ * ghrow[2 * Dd + d]);
                float h = hrow[d];
                float p = (1.f - z) * n_ + z * h;
                Ps[i * Dd + d] = p;
                Pout[((size_t)b * Nn_ + i) * Dd + d] = p;
                kp += p * wk[d];
            }
            red[t] = kp;
            __syncthreads();
            for (int s = 128; s; s >>= 1) {
                if (t < s) red[t] += red[t + s];
                __syncthreads();
            }
            if (t == 0) kap[i] = red[0];
            __syncthreads();
        }
    }
}

// ---------------- deferred c combine: CL = GRU(GIc, GHc, h=Mall) ----------------
__global__ void combine_c(const float* __restrict__ GIc, const float* __restrict__ GHc,
                          const float* __restrict__ Mall, float* __restrict__ CL) {
    int idx = blockIdx.x * blockDim.x + threadIdx.x;
    if (idx >= BN_ * Dd) return;
    int row = idx / Dd, d = idx % Dd;
    const float* gi = GIc + (size_t)row * G3;
    const float* gh = GHc + (size_t)row * G3;
    float r_ = sigf(gi[d] + gh[d]);
    float z = sigf(gi[Dd + d] + gh[Dd + d]);
    float n_ = tanhf(gi[2 * Dd + d] + r_ * gh[2 * Dd + d]);
    float h = Mall[idx];
    CL[idx] = (1.f - z) * n_ + z * h;
}

// ---------------- concat copy ----------------
__global__ void copy_seg(const float* __restrict__ src, float* __restrict__ dst,
                         int width, int off) {
    int idx = blockIdx.x * blockDim.x + threadIdx.x;
    if (idx >= BN_ * width) return;
    int row = idx / width, c = idx % width;
    dst[(size_t)row * IN_DIM + off + c] = src[(size_t)row * width + c];
}

// ---------------- launch ----------------
extern "C" void kernel_launch(void* const* d_in, const int* in_sizes, int n_in,
                              void* d_out, int out_size) {
    const float* features = (const float*)d_in[0];
    const float* adj = (const float*)d_in[1];
    const float* fc1_w = (const float*)d_in[3];
    const float* fc1_b = (const float*)d_in[4];
    const float* gc_wih = (const float*)d_in[5];
    const float* gc_whh = (const float*)d_in[6];
    const float* gc_bih = (const float*)d_in[7];
    const float* gc_bhh = (const float*)d_in[8];
    const float* gp_wih = (const float*)d_in[9];
    const float* gp_whh = (const float*)d_in[10];
    const float* gp_bih = (const float*)d_in[11];
    const float* gp_bhh = (const float*)d_in[12];
    const float* gat_wq = (const float*)d_in[13];
    const float* gat_wk = (const float*)d_in[14];
    const float* gat_b = (const float*)d_in[15];
    const float* mlp_w0 = (const float*)d_in[16];
    const float* mlp_b0 = (const float*)d_in[17];
    const float* mlp_w1 = (const float*)d_in[18];
    const float* mlp_b1 = (const float*)d_in[19];
    const float* mlp_w2 = (const float*)d_in[20];
    const float* mlp_b2 = (const float*)d_in[21];
    float* out = (float*)d_out;

    float *H0, *CLb, *Pb, *GIc, *GHp, *GHc, *Mall, *qdot, *Hcat, *x1, *x2;
    __half *pwiTh, *pwhTh;
    cudaGetSymbolAddress((void**)&H0, d_H0);
    cudaGetSymbolAddress((void**)&CLb, d_CL);
    cudaGetSymbolAddress((void**)&Pb, d_Pl);
    cudaGetSymbolAddress((void**)&GIc, d_GIc);
    cudaGetSymbolAddress((void**)&GHp, d_GHp);
    cudaGetSymbolAddress((void**)&GHc, d_GHc);
    cudaGetSymbolAddress((void**)&Mall, d_Mall);
    cudaGetSymbolAddress((void**)&qdot, d_qdot);
    cudaGetSymbolAddress((void**)&pwiTh, d_pwiTh);
    cudaGetSymbolAddress((void**)&pwhTh, d_pwhTh);
    cudaGetSymbolAddress((void**)&Hcat, d_Hcat);
    cudaGetSymbolAddress((void**)&x1, d_x1);
    cudaGetSymbolAddress((void**)&x2, d_x2);

    cudaFuncSetAttribute(scan_layer, cudaFuncAttributeMaxDynamicSharedMemorySize,
                         SCAN_SMEM_BYTES);

    // transpose+convert+pad p-GRU weights (inside graph; deterministic)
    {
        int tot = Ll * Dd * G3P;
        transpose_weights<<<(tot + 255) / 256, 256>>>(gp_wih, gp_whh, pwiTh, pwhTh);
    }

    // H0 = relu(features @ fc1_w + fc1_b)
    {
        dim3 g((Dd + GT_BN - 1) / GT_BN, (BN_ + GT_BM - 1) / GT_BM);
        gemm_tc<false, 1><<<g, 256>>>(features, fc1_w, fc1_b, H0, BN_, Dd, Ee);
    }

    float* CL_l[Ll];
    float* P_l[Ll];
    for (int l = 0; l < Ll; l++) {
        CL_l[l] = CLb + (size_t)l * BN_ * Dd;
        P_l[l] = Pb + (size_t)l * BN_ * Dd;
    }
    const float* Cin_l[Ll] = {H0, CL_l[0], CL_l[1], CL_l[2]};

    dim3 g900((G3 + GT_BN - 1) / GT_BN, (BN_ + GT_BM - 1) / GT_BM);
    for (int l = 0; l < Ll; l++) {
        const float* Cin = Cin_l[l];
        const float* Hin = (l == 0) ? H0 : (l == 1) ? CL_l[0] : (l == 2) ? P_l[0] : CL_l[1];
        const float* cwi = gc_wih + (size_t)l * G3 * Dd;
        const float* cwh = gc_whh + (size_t)l * G3 * Dd;
        const float* cbi = gc_bih + (size_t)l * G3;
        const float* cbh = gc_bhh + (size_t)l * G3;
        const float* pwh = gp_whh + (size_t)l * G3 * Dd;
        const float* pbi = gp_bih + (size_t)l * G3;
        const float* pbh = gp_bhh + (size_t)l * G3;
        const float* wq = gat_wq + (size_t)l * Dd;
        const float* wk = gat_wk + (size_t)l * Dd;
        const float* gb = gat_b + l;
        const __half* Wi = pwiTh + (size_t)l * Dd * G3P;
        const __half* Wh = pwhTh + (size_t)l * Dd * G3P;

        // batched precomputes
        gemm_tc<true, 0><<<g900, 256>>>(Cin, cwi, cbi, GIc, BN_, G3, Dd);
        gemm_tc<true, 0><<<g900, 256>>>(Hin, pwh, pbh, GHp, BN_, G3, Dd);
        qdot_kernel<<<(BN_ + 7) / 8, 256>>>(Cin, wq, qdot);

        // whole 96-step recurrence: one persistent kernel, one block per batch
        scan_layer<<<Bb, 256, SCAN_SMEM_BYTES>>>(Cin, Hin, GHp, qdot, adj, Wi, Wh,
                                                 pbi, pbh, wk, gb, P_l[l], Mall);

        // deferred c-GRU
        gemm_tc<true, 0><<<g900, 256>>>(Mall, cwh, cbh, GHc, BN_, G3, Dd);
        combine_c<<<(BN_ * Dd + 255) / 256, 256>>>(GIc, GHc, Mall, CL_l[l]);
    }

    // concat: [H0, CL0, P0, CL1, P1, CL2, P2, CL3, P3, features]
    {
        const float* segs[9] = {H0, CL_l[0], P_l[0], CL_l[1], P_l[1],
                                CL_l[2], P_l[2], CL_l[3], P_l[3]};
        int nb = (BN_ * Dd + 255) / 256;
        for (int s = 0; s < 9; s++) copy_seg<<<nb, 256>>>(segs[s], Hcat, Dd, s * Dd);
        int nbf = (BN_ * Ee + 255) / 256;
        copy_seg<<<nbf, 256>>>(features, Hcat, Ee, 9 * Dd);
    }

    // MLP
    {
        dim3 g0((Dd + GT_BN - 1) / GT_BN, (BN_ + GT_BM - 1) / GT_BM);
        gemm_tc<false, 1><<<g0, 256>>>(Hcat, mlp_w0, mlp_b0, x1, BN_, Dd, IN_DIM);
        gemm_tc<false, 1><<<g0, 256>>>(x1, mlp_w1, mlp_b1, x2, BN_, Dd, Dd);
        dim3 g2((NCc + GT_BN - 1) / GT_BN, (BN_ + GT_BM - 1) / GT_BM);
        gemm_tc<false, 0><<<g2, 256>>>(x2, mlp_w2, mlp_b2, out, BN_, NCc, Dd);
    }
}

// round 9
// speedup vs baseline: 2.0623x; 2.0623x over previous
#include <cuda_runtime.h>
#include <cuda_fp16.h>
#include <cstdint>

#define Bb 48
#define Nn_ 96
#define Ee 1024
#define Dd 300
#define G3 900
#define G3P 904                          // padded to 113*8 for uint4 loads
#define Ll 4
#define NCc 7
#define BN_ (Bb * Nn_)                   // 4608
#define IN_DIM (Dd * (2 * Ll + 1) + Ee)  // 3724

// ---------------- scratch (static device arrays; no allocation) ----------------
__device__ float d_H0[BN_ * Dd];
__device__ float d_CL[Ll][BN_ * Dd];
__device__ float d_Pl[Ll][BN_ * Dd];
__device__ float d_GIc[BN_ * G3];
__device__ float d_GHp[BN_ * G3];
__device__ float d_GHc[BN_ * G3];
__device__ float d_Mall[BN_ * Dd];
__device__ float d_qdot[BN_];
__device__ __half d_pwiTh[Ll * Dd * G3P];  // k-major fp16 padded: [l][k][r<904]
__device__ __half d_pwhTh[Ll * Dd * G3P];
__device__ float d_Hcat[(size_t)BN_ * IN_DIM];
__device__ float d_x1[BN_ * Dd];
__device__ float d_x2[BN_ * Dd];

__device__ __forceinline__ float sigf(float x) { return 1.f / (1.f + expf(-x)); }

// ---- transpose+convert+pad: (L,900,300) fp32 -> (L,300,904) fp16, zeros in pad ----
__global__ void transpose_weights(const float* __restrict__ wih,
                                  const float* __restrict__ whh,
                                  __half* __restrict__ wihT,
                                  __half* __restrict__ whhT) {
    int idx = blockIdx.x * blockDim.x + threadIdx.x;
    if (idx >= Ll * Dd * G3P) return;
    int l = idx / (Dd * G3P);
    int rem = idx % (Dd * G3P);
    int k = rem / G3P;
    int r = rem % G3P;
    float vi = 0.f, vh = 0.f;
    if (r < G3) {
        size_t src = ((size_t)l * G3 + r) * Dd + k;
        vi = wih[src];
        vh = whh[src];
    }
    wihT[idx] = __float2half(vi);
    whhT[idx] = __float2half(vh);
}

// ================= 3xTF32 tensor-core GEMM (fp32-accurate) =================
// C(M,N) = A(M,K) @ op(B) + bias; op(B)=B(K,N) if !TRANSB else B(N,K)^T
// Block tile 128x64x16; 8 warps 4(M)x2(N); warp tile 32x32 via m16n8k8.
// hi/lo tf32 split staged in SMEM once; D += Al*Bh + Ah*Bl + Ah*Bh.
#define GT_BM 128
#define GT_BN 64
#define GT_BK 16
#define GT_BMP 133  // odd mod-32 stride: conflict-free
#define GT_BNP 69

__device__ __forceinline__ uint32_t f2tf(float f) {
    uint32_t r;
    asm("cvt.rna.tf32.f32 %0, %1;" : "=r"(r) : "f"(f));
    return r;
}

__device__ __forceinline__ void mma_tf32(float* c, const uint32_t* a, uint32_t b0,
                                         uint32_t b1) {
    asm("mma.sync.aligned.m16n8k8.row.col.f32.tf32.tf32.f32 "
        "{%0,%1,%2,%3}, {%4,%5,%6,%7}, {%8,%9}, {%0,%1,%2,%3};"
        : "+f"(c[0]), "+f"(c[1]), "+f"(c[2]), "+f"(c[3])
        : "r"(a[0]), "r"(a[1]), "r"(a[2]), "r"(a[3]), "r"(b0), "r"(b1));
}

template <bool TRANSB, int ACT>
__global__ void __launch_bounds__(256, 2)
gemm_tc(const float* __restrict__ A, const float* __restrict__ Bm,
        const float* __restrict__ bias, float* __restrict__ C,
        int M, int Nc, int K) {
    __shared__ float As_h[GT_BK][GT_BMP];
    __shared__ float As_l[GT_BK][GT_BMP];
    __shared__ float Bs_h[GT_BK][GT_BNP];
    __shared__ float Bs_l[GT_BK][GT_BNP];
    int tid = threadIdx.x;  // 256
    int bm = blockIdx.y * GT_BM;
    int bn = blockIdx.x * GT_BN;
    int wid = tid >> 5;
    int lane = tid & 31;
    int warpM = wid >> 1;  // 0..3
    int warpN = wid & 1;   // 0..1
    int l4 = lane & 3;
    int g = lane >> 2;

    float acc[2][4][4] = {};  // [mf][nf][reg]

    for (int k0 = 0; k0 < K; k0 += GT_BK) {
        // stage A (split hi/lo once): As[k][m] = A[bm+m][k0+k]
#pragma unroll
        for (int e = tid; e < GT_BM * GT_BK; e += 256) {
            int r = e >> 4, c = e & 15;
            int gm = bm + r, gk = k0 + c;
            float v = (gm < M && gk < K) ? A[(size_t)gm * K + gk] : 0.f;
            uint32_t h = f2tf(v);
            As_h[c][r] = __uint_as_float(h);
            As_l[c][r] = __uint_as_float(f2tf(v - __uint_as_float(h)));
        }
        // stage B: Bs[k][n] = op(B)[k0+k][bn+n]
#pragma unroll
        for (int e = tid; e < GT_BN * GT_BK; e += 256) {
            int n, c;
            float v;
            if (TRANSB) {
                n = e >> 4; c = e & 15;
                int gn = bn + n, gk = k0 + c;
                v = (gn < Nc && gk < K) ? Bm[(size_t)gn * K + gk] : 0.f;
            } else {
                c = e >> 6; n = e & 63;
                int gk = k0 + c, gn = bn + n;
                v = (gk < K && gn < Nc) ? Bm[(size_t)gk * Nc + gn] : 0.f;
            }
            uint32_t h = f2tf(v);
            Bs_h[c][n] = __uint_as_float(h);
            Bs_l[c][n] = __uint_as_float(f2tf(v - __uint_as_float(h)));
        }
        __syncthreads();
#pragma unroll
        for (int kc = 0; kc < 2; kc++) {
            int kb = kc * 8;
            // A fragments: a0=(g,l4) a1=(g+8,l4) a2=(g,l4+4) a3=(g+8,l4+4)
            uint32_t ah[2][4], al[2][4];
#pragma unroll
            for (int mf = 0; mf < 2; mf++) {
                int mb = warpM * 32 + mf * 16;
                ah[mf][0] = __float_as_uint(As_h[kb + l4][mb + g]);
                ah[mf][1] = __float_as_uint(As_h[kb + l4][mb + g + 8]);
                ah[mf][2] = __float_as_uint(As_h[kb + l4 + 4][mb + g]);
                ah[mf][3] = __float_as_uint(As_h[kb + l4 + 4][mb + g + 8]);
                al[mf][0] = __float_as_uint(As_l[kb + l4][mb + g]);
                al[mf][1] = __float_as_uint(As_l[kb + l4][mb + g + 8]);
                al[mf][2] = __float_as_uint(As_l[kb + l4 + 4][mb + g]);
                al[mf][3] = __float_as_uint(As_l[kb + l4 + 4][mb + g + 8]);
            }
#pragma unroll
            for (int nf = 0; nf < 4; nf++) {
                int nb = warpN * 32 + nf * 8;
                uint32_t bh0 = __float_as_uint(Bs_h[kb + l4][nb + g]);
                uint32_t bh1 = __float_as_uint(Bs_h[kb + l4 + 4][nb + g]);
                uint32_t bl0 = __float_as_uint(Bs_l[kb + l4][nb + g]);
                uint32_t bl1 = __float_as_uint(Bs_l[kb + l4 + 4][nb + g]);
#pragma unroll
                for (int mf = 0; mf < 2; mf++) {
                    mma_tf32(acc[mf][nf], al[mf], bh0, bh1);  // Al*Bh
                    mma_tf32(acc[mf][nf], ah[mf], bl0, bl1);  // Ah*Bl
                    mma_tf32(acc[mf][nf], ah[mf], bh0, bh1);  // Ah*Bh
                }
            }
        }
        __syncthreads();
    }

    // epilogue: c0:(g,2*l4) c1:(g,2*l4+1) c2:(g+8,2*l4) c3:(g+8,2*l4+1)
#pragma unroll
    for (int mf = 0; mf < 2; mf++) {
#pragma unroll
        for (int nf = 0; nf < 4; nf++) {
            int gm0 = bm + warpM * 32 + mf * 16 + g;
            int gn0 = bn + warpN * 32 + nf * 8 + 2 * l4;
#pragma unroll
            for (int hi = 0; hi < 2; hi++) {
                int gm = gm0 + hi * 8;
                if (gm >= M) continue;
#pragma unroll
                for (int jj = 0; jj < 2; jj++) {
                    int gn = gn0 + jj;
                    if (gn >= Nc) continue;
                    float v = acc[mf][nf][hi * 2 + jj] + bias[gn];
                    if (ACT == 1) v = fmaxf(v, 0.f);
                    C[(size_t)gm * Nc + gn] = v;
                }
            }
        }
    }
}

// ---------------- qdot[b,i] = Cin[b,i,:] . wq ----------------
__global__ void qdot_kernel(const float* __restrict__ Cin, const float* __restrict__ wq,
                            float* __restrict__ qdot) {
    int row = blockIdx.x * (blockDim.x / 32) + (threadIdx.x / 32);
    int lane = threadIdx.x & 31;
    if (row >= BN_) return;
    float s = 0.f;
    for (int k = lane; k < Dd; k += 32) s += Cin[(size_t)row * Dd + k] * wq[k];
#pragma unroll
    for (int o = 16; o; o >>= 1) s += __shfl_down_sync(0xffffffffu, s, o);
    if (lane == 0) qdot[row] = s;
}

// ================ persistent per-batch scan (512 threads) ================
#define SCT 512
#define SCAN_SMEM_FLOATS (Nn_ * Dd + 304 + G3P + Nn_ + Nn_ + 32 + 3 * G3P)
#define SCAN_SMEM_BYTES (SCAN_SMEM_FLOATS * 4)

__device__ __forceinline__ float warp_sum(float v) {
#pragma unroll
    for (int o = 16; o; o >>= 1) v += __shfl_down_sync(0xffffffffu, v, o);
    return v;
}
__device__ __forceinline__ float warp_max(float v) {
#pragma unroll
    for (int o = 16; o; o >>= 1) v = fmaxf(v, __shfl_down_sync(0xffffffffu, v, o));
    return v;
}

// 512-thread block reduce. ALL threads must call.
__device__ __forceinline__ float block_sum(float v, float* red, int t) {
    int wid = t >> 5, lane = t & 31;
    v = warp_sum(v);
    if (lane == 0) red[wid] = v;
    __syncthreads();
    if (wid == 0) {
        float x = (lane < 16) ? red[lane] : 0.f;
        x = warp_sum(x);
        if (lane == 0) red[16] = x;
    }
    __syncthreads();
    float r = red[16];
    __syncthreads();
    return r;
}
__device__ __forceinline__ float block_max(float v, float* red, int t) {
    int wid = t >> 5, lane = t & 31;
    v = warp_max(v);
    if (lane == 0) red[wid] = v;
    __syncthreads();
    if (wid == 0) {
        float x = (lane < 16) ? red[lane] : -1e30f;
        x = warp_max(x);
        if (lane == 0) red[16] = x;
    }
    __syncthreads();
    float r = red[16];
    __syncthreads();
    return r;
}

// gi[r] = sum_k Ms[k]*W[k][r] + bias[r]; W fp16 k-major padded to 904.
// 4-way split-K: thread t<452: quarter q=t/113 covers k in [75q,75q+75),
// rowgroup rg=t%113 covers rows [8rg,8rg+8) via one LDG.128 per k.
// ALL 512 threads must call (contains __syncthreads).
__device__ __forceinline__ void matvec_452(const __half* __restrict__ W,
                                           const float* __restrict__ bias,
                                           const float* __restrict__ Ms,
                                           float* __restrict__ gi,
                                           float* __restrict__ part, int t) {
    float a0 = 0.f, a1 = 0.f, a2 = 0.f, a3 = 0.f;
    float a4 = 0.f, a5 = 0.f, a6 = 0.f, a7 = 0.f;
    int q = 0, rg = 0;
    if (t < 452) {
        q = t / 113;
        rg = t - q * 113;
        int k0 = q * 75;
        const uint4* wp = (const uint4*)W;  // 113 uint4 per k-row
#pragma unroll 5
        for (int k = k0; k < k0 + 75; k++) {
            float m = Ms[k];
            uint4 wv = wp[(size_t)k * 113 + rg];
            float2 f0 = __half22float2(*reinterpret_cast<const __half2*>(&wv.x));
            float2 f1 = __half22float2(*reinterpret_cast<const __half2*>(&wv.y));
            float2 f2 = __half22float2(*reinterpret_cast<const __half2*>(&wv.z));
            float2 f3 = __half22float2(*reinterpret_cast<const __half2*>(&wv.w));
            a0 += m * f0.x; a1 += m * f0.y;
            a2 += m * f1.x; a3 += m * f1.y;
            a4 += m * f2.x; a5 += m * f2.y;
            a6 += m * f3.x; a7 += m * f3.y;
        }
    }
    if (t >= 113 && t < 452) {
        float* p = part + (size_t)(q - 1) * G3P + rg * 8;
        p[0] = a0; p[1] = a1; p[2] = a2; p[3] = a3;
        p[4] = a4; p[5] = a5; p[6] = a6; p[7] = a7;
    }
    __syncthreads();
    if (t < 113) {
        int r = t * 8;
        float v[8] = {a0, a1, a2, a3, a4, a5, a6, a7};
#pragma unroll
        for (int j = 0; j < 8; j++) {
            int rr = r + j;
            if (rr < G3)
                gi[rr] = v[j] + part[rr] + part[G3P + rr] + part[2 * G3P + rr] + bias[rr];
        }
    }
    __syncthreads();
}

__global__ void __launch_bounds__(SCT, 1)
scan_layer(const float* __restrict__ Cin, const float* __restrict__ Hin,
           const float* __restrict__ GHp, const float* __restrict__ qdot,
           const float* __restrict__ adj, const __half* __restrict__ Wi,
           const __half* __restrict__ Wh, const float* __restrict__ pbi,
           const float* __restrict__ pbh, const float* __restrict__ wk,
           const float* __restrict__ gbp, float* __restrict__ Pout,
           float* __restrict__ Mall) {
    extern __shared__ float sm[];
    float* Ps = sm;             // 96*300
    float* Ms = Ps + Nn_ * Dd;  // 304
    float* gi = Ms + 304;       // 904
    float* wsm = gi + G3P;      // 96
    float* kap = wsm + Nn_;     // 96
    float* red = kap + Nn_;     // 32
    float* part = red + 32;     // 3*904

    int b = blockIdx.x;
    int t = threadIdx.x;
    float gb = gbp[0];

    // ---- step 0: p0 = GRU(x=0, h=Cin[b,0,:]) ----
    if (t < Dd) Ms[t] = Cin[((size_t)b * Nn_) * Dd + t];
    __syncthreads();
    matvec_452(Wh, pbh, Ms, gi, part, t);  // gh = h @ pwh^T + pbh
    {
        float kp = 0.f;
        if (t < Dd) {
            int d = t;
            float r_ = sigf(pbi[d] + gi[d]);
            float z = sigf(pbi[Dd + d] + gi[Dd + d]);
            float n_ = tanhf(pbi[2 * Dd + d] + r_ * gi[2 * Dd + d]);
            float h = Ms[d];
            float p = (1.f - z) * n_ + z * h;
            Ps[d] = p;
            Pout[((size_t)b * Nn_) * Dd + d] = p;
            Mall[((size_t)b * Nn_) * Dd + d] = 0.f;
            kp = p * wk[d];
        }
        kp = block_sum(kp, red, t);
        if (t == 0) kap[0] = kp;
        __syncthreads();
    }

    // ---- steps 1..95 ----
    for (int i = 1; i < Nn_; i++) {
        // prefetch GRU gmem operands (independent of in-step work); latency
        // overlaps softmax + M accumulation + matvec below.
        float gh0 = 0.f, gh1 = 0.f, gh2 = 0.f, hh = 0.f;
        if (t < Dd) {
            const float* ghrow = GHp + ((size_t)b * Nn_ + i) * G3;
            gh0 = ghrow[t];
            gh1 = ghrow[Dd + t];
            gh2 = ghrow[2 * Dd + t];
            hh = Hin[((size_t)b * Nn_ + i) * Dd + t];
        }

        // attention softmax over j < i (masked by adj)
        float qd = qdot[b * Nn_ + i];
        float aval = -1e30f;
        if (t < i) {
            float m = adj[((size_t)b * Nn_ + i) * Nn_ + t];
            if (m != 0.f) aval = qd + kap[t] + gb;
        }
        float mx = block_max(aval, red, t);
        float e = (aval > -1e29f) ? __expf(aval - mx) : 0.f;
        float s = block_sum(e, red, t);
        float inv = 1.f / s;
        if (t < Nn_) wsm[t] = e * inv;
        __syncthreads();

        // M = sum_j w_j * P_j (SMEM-resident P)
        if (t < Dd) {
            int d = t;
            float m = 0.f;
            for (int j = 0; j < i; j++) m += wsm[j] * Ps[j * Dd + d];
            Ms[d] = m;
            Mall[((size_t)b * Nn_ + i) * Dd + d] = m;
        }
        __syncthreads();

        // gi = M @ pwi^T + pbi (fp16 4-way split-K matvec)
        matvec_452(Wi, pbi, Ms, gi, part, t);

        // p_i = GRU(gi, prefetched GHp row, prefetched Hin row); P; kappa_i
        {
            float kp = 0.f;
            if (t < Dd) {
                int d = t;
                float r_ = sigf(gi[d] + gh0);
                float z = sigf(gi[Dd + d] + gh1);
                float n_ = tanhf(gi[2 * Dd + d] + r_ * gh2);
                float p = (1.f - z) * n_ + z * hh;
                Ps[i * Dd + d] = p;
                Pout[((size_t)b * Nn_ + i) * Dd + d] = p;
                kp = p * wk[d];
            }
            kp = block_sum(kp, red, t);
            if (t == 0) kap[i] = kp;
            __syncthreads();
        }
    }
}

// ---------------- deferred c combine: CL = GRU(GIc, GHc, h=Mall) ----------------
__global__ void combine_c(const float* __restrict__ GIc, const float* __restrict__ GHc,
                          const float* __restrict__ Mall, float* __restrict__ CL) {
    int idx = blockIdx.x * blockDim.x + threadIdx.x;
    if (idx >= BN_ * Dd) return;
    int row = idx / Dd, d = idx % Dd;
    const float* gi = GIc + (size_t)row * G3;
    const float* gh = GHc + (size_t)row * G3;
    float r_ = sigf(gi[d] + gh[d]);
    float z = sigf(gi[Dd + d] + gh[Dd + d]);
    float n_ = tanhf(gi[2 * Dd + d] + r_ * gh[2 * Dd + d]);
    float h = Mall[idx];
    CL[idx] = (1.f - z) * n_ + z * h;
}

// ---------------- concat copy ----------------
__global__ void copy_seg(const float* __restrict__ src, float* __restrict__ dst,
                         int width, int off) {
    int idx = blockIdx.x * blockDim.x + threadIdx.x;
    if (idx >= BN_ * width) return;
    int row = idx / width, c = idx % width;
    dst[(size_t)row * IN_DIM + off + c] = src[(size_t)row * width + c];
}

// ---------------- launch ----------------
extern "C" void kernel_launch(void* const* d_in, const int* in_sizes, int n_in,
                              void* d_out, int out_size) {
    const float* features = (const float*)d_in[0];
    const float* adj = (const float*)d_in[1];
    const float* fc1_w = (const float*)d_in[3];
    const float* fc1_b = (const float*)d_in[4];
    const float* gc_wih = (const float*)d_in[5];
    const float* gc_whh = (const float*)d_in[6];
    const float* gc_bih = (const float*)d_in[7];
    const float* gc_bhh = (const float*)d_in[8];
    const float* gp_wih = (const float*)d_in[9];
    const float* gp_whh = (const float*)d_in[10];
    const float* gp_bih = (const float*)d_in[11];
    const float* gp_bhh = (const float*)d_in[12];
    const float* gat_wq = (const float*)d_in[13];
    const float* gat_wk = (const float*)d_in[14];
    const float* gat_b = (const float*)d_in[15];
    const float* mlp_w0 = (const float*)d_in[16];
    const float* mlp_b0 = (const float*)d_in[17];
    const float* mlp_w1 = (const float*)d_in[18];
    const float* mlp_b1 = (const float*)d_in[19];
    const float* mlp_w2 = (const float*)d_in[20];
    const float* mlp_b2 = (const float*)d_in[21];
    float* out = (float*)d_out;

    float *H0, *CLb, *Pb, *GIc, *GHp, *GHc, *Mall, *qdot, *Hcat, *x1, *x2;
    __half *pwiTh, *pwhTh;
    cudaGetSymbolAddress((void**)&H0, d_H0);
    cudaGetSymbolAddress((void**)&CLb, d_CL);
    cudaGetSymbolAddress((void**)&Pb, d_Pl);
    cudaGetSymbolAddress((void**)&GIc, d_GIc);
    cudaGetSymbolAddress((void**)&GHp, d_GHp);
    cudaGetSymbolAddress((void**)&GHc, d_GHc);
    cudaGetSymbolAddress((void**)&Mall, d_Mall);
    cudaGetSymbolAddress((void**)&qdot, d_qdot);
    cudaGetSymbolAddress((void**)&pwiTh, d_pwiTh);
    cudaGetSymbolAddress((void**)&pwhTh, d_pwhTh);
    cudaGetSymbolAddress((void**)&Hcat, d_Hcat);
    cudaGetSymbolAddress((void**)&x1, d_x1);
    cudaGetSymbolAddress((void**)&x2, d_x2);

    cudaFuncSetAttribute(scan_layer, cudaFuncAttributeMaxDynamicSharedMemorySize,
                         SCAN_SMEM_BYTES);

    // transpose+convert+pad p-GRU weights (inside graph; deterministic)
    {
        int tot = Ll * Dd * G3P;
        transpose_weights<<<(tot + 255) / 256, 256>>>(gp_wih, gp_whh, pwiTh, pwhTh);
    }

    // H0 = relu(features @ fc1_w + fc1_b)
    {
        dim3 g((Dd + GT_BN - 1) / GT_BN, (BN_ + GT_BM - 1) / GT_BM);
        gemm_tc<false, 1><<<g, 256>>>(features, fc1_w, fc1_b, H0, BN_, Dd, Ee);
    }

    float* CL_l[Ll];
    float* P_l[Ll];
    for (int l = 0; l < Ll; l++) {
        CL_l[l] = CLb + (size_t)l * BN_ * Dd;
        P_l[l] = Pb + (size_t)l * BN_ * Dd;
    }
    const float* Cin_l[Ll] = {H0, CL_l[0], CL_l[1], CL_l[2]};

    dim3 g900((G3 + GT_BN - 1) / GT_BN, (BN_ + GT_BM - 1) / GT_BM);
    for (int l = 0; l < Ll; l++) {
        const float* Cin = Cin_l[l];
        const float* Hin = (l == 0) ? H0 : (l == 1) ? CL_l[0] : (l == 2) ? P_l[0] : CL_l[1];
        const float* cwi = gc_wih + (size_t)l * G3 * Dd;
        const float* cwh = gc_whh + (size_t)l * G3 * Dd;
        const float* cbi = gc_bih + (size_t)l * G3;
        const float* cbh = gc_bhh + (size_t)l * G3;
        const float* pwh = gp_whh + (size_t)l * G3 * Dd;
        const float* pbi = gp_bih + (size_t)l * G3;
        const float* pbh = gp_bhh + (size_t)l * G3;
        const float* wq = gat_wq + (size_t)l * Dd;
        const float* wk = gat_wk + (size_t)l * Dd;
        const float* gb = gat_b + l;
        const __half* Wi = pwiTh + (size_t)l * Dd * G3P;
        const __half* Wh = pwhTh + (size_t)l * Dd * G3P;

        // batched precomputes
        gemm_tc<true, 0><<<g900, 256>>>(Cin, cwi, cbi, GIc, BN_, G3, Dd);
        gemm_tc<true, 0><<<g900, 256>>>(Hin, pwh, pbh, GHp, BN_, G3, Dd);
        qdot_kernel<<<(BN_ + 7) / 8, 256>>>(Cin, wq, qdot);

        // whole 96-step recurrence: one persistent kernel, one block per batch
        scan_layer<<<Bb, SCT, SCAN_SMEM_BYTES>>>(Cin, Hin, GHp, qdot, adj, Wi, Wh,
                                                 pbi, pbh, wk, gb, P_l[l], Mall);

        // deferred c-GRU
        gemm_tc<true, 0><<<g900, 256>>>(Mall, cwh, cbh, GHc, BN_, G3, Dd);
        combine_c<<<(BN_ * Dd + 255) / 256, 256>>>(GIc, GHc, Mall, CL_l[l]);
    }

    // concat: [H0, CL0, P0, CL1, P1, CL2, P2, CL3, P3, features]
    {
        const float* segs[9] = {H0, CL_l[0], P_l[0], CL_l[1], P_l[1],
                                CL_l[2], P_l[2], CL_l[3], P_l[3]};
        int nb = (BN_ * Dd + 255) / 256;
        for (int s = 0; s < 9; s++) copy_seg<<<nb, 256>>>(segs[s], Hcat, Dd, s * Dd);
        int nbf = (BN_ * Ee + 255) / 256;
        copy_seg<<<nbf, 256>>>(features, Hcat, Ee, 9 * Dd);
    }

    // MLP
    {
        dim3 g0((Dd + GT_BN - 1) / GT_BN, (BN_ + GT_BM - 1) / GT_BM);
        gemm_tc<false, 1><<<g0, 256>>>(Hcat, mlp_w0, mlp_b0, x1, BN_, Dd, IN_DIM);
        gemm_tc<false, 1><<<g0, 256>>>(x1, mlp_w1, mlp_b1, x2, BN_, Dd, Dd);
        dim3 g2((NCc + GT_BN - 1) / GT_BN, (BN_ + GT_BM - 1) / GT_BM);
        gemm_tc<false, 0><<<g2, 256>>>(x2, mlp_w2, mlp_b2, out, BN_, NCc, Dd);
    }
}

// round 16
// speedup vs baseline: 2.2625x; 1.0971x over previous
#include <cuda_runtime.h>
#include <cuda_fp16.h>
#include <cstdint>

#define Bb 48
#define Nn_ 96
#define Ee 1024
#define Dd 300
#define G3 900
#define G3P 904                          // padded to 113*8 for uint4 loads
#define Ll 4
#define NCc 7
#define BN_ (Bb * Nn_)                   // 4608
#define IN_DIM (Dd * (2 * Ll + 1) + Ee)  // 3724

// ---------------- scratch (static device arrays; no allocation) ----------------
__device__ float d_H0[BN_ * Dd];
__device__ float d_CL[Ll][BN_ * Dd];
__device__ float d_Pl[Ll][BN_ * Dd];
__device__ float d_GIc[BN_ * G3];
__device__ float d_GHp[BN_ * G3];
__device__ float d_GHc[BN_ * G3];
__device__ float d_Mall[BN_ * Dd];
__device__ float d_qdot[BN_];
__device__ __half d_pwiTh[Ll * Dd * G3P];  // k-major fp16 padded: [l][k][r<904]
__device__ __half d_pwhTh[Ll * Dd * G3P];
__device__ float d_Hcat[(size_t)BN_ * IN_DIM];
__device__ float d_x1[BN_ * Dd];
__device__ float d_x2[BN_ * Dd];

__device__ __forceinline__ float sigf(float x) { return 1.f / (1.f + expf(-x)); }

// ---- transpose+convert+pad: (L,900,300) fp32 -> (L,300,904) fp16, zeros in pad ----
__global__ void transpose_weights(const float* __restrict__ wih,
                                  const float* __restrict__ whh,
                                  __half* __restrict__ wihT,
                                  __half* __restrict__ whhT) {
    int idx = blockIdx.x * blockDim.x + threadIdx.x;
    if (idx >= Ll * Dd * G3P) return;
    int l = idx / (Dd * G3P);
    int rem = idx % (Dd * G3P);
    int k = rem / G3P;
    int r = rem % G3P;
    float vi = 0.f, vh = 0.f;
    if (r < G3) {
        size_t src = ((size_t)l * G3 + r) * Dd + k;
        vi = wih[src];
        vh = whh[src];
    }
    wihT[idx] = __float2half(vi);
    whhT[idx] = __float2half(vh);
}

// ================= tf32 tensor-core GEMM, cp.async double-buffered =================
// C(M,N) = A(M,K) @ op(B) + bias; op(B)=B(K,N) if !TRANSB else B(N,K)^T
// Block tile 128x64x16; 8 warps 4(M)x2(N); warp tile 32x32 via m16n8k8.
// PREC=1: single-pass tf32 (inputs rounded rna). PREC=3: 3xTF32 (fp32-class).
#define GT_BM 128
#define GT_BN 64
#define GT_BK 16
#define GT_BMP 133  // odd mod-32 stride
#define GT_BNP 69

__device__ __forceinline__ uint32_t f2tf(float f) {
    uint32_t r;
    asm("cvt.rna.tf32.f32 %0, %1;" : "=r"(r) : "f"(f));
    return r;
}

__device__ __forceinline__ void cp4(uint32_t dst, const float* src, bool ok) {
    asm volatile("cp.async.ca.shared.global [%0], [%1], 4, %2;"
                 :: "r"(dst), "l"(src), "r"(ok ? 4u : 0u));
}
__device__ __forceinline__ void cp_commit() {
    asm volatile("cp.async.commit_group;" ::: "memory");
}
template <int N>
__device__ __forceinline__ void cp_wait() {
    asm volatile("cp.async.wait_group %0;" :: "n"(N) : "memory");
}

__device__ __forceinline__ void mma_tf32(float* c, const uint32_t* a, uint32_t b0,
                                         uint32_t b1) {
    asm("mma.sync.aligned.m16n8k8.row.col.f32.tf32.tf32.f32 "
        "{%0,%1,%2,%3}, {%4,%5,%6,%7}, {%8,%9}, {%0,%1,%2,%3};"
        : "+f"(c[0]), "+f"(c[1]), "+f"(c[2]), "+f"(c[3])
        : "r"(a[0]), "r"(a[1]), "r"(a[2]), "r"(a[3]), "r"(b0), "r"(b1));
}

template <bool TRANSB, int ACT, int PREC>
__global__ void __launch_bounds__(256, 2)
gemm_tc(const float* __restrict__ A, const float* __restrict__ Bm,
        const float* __restrict__ bias, float* __restrict__ C,
        int M, int Nc, int K) {
    __shared__ float As[2][GT_BK][GT_BMP];  // raw fp32, k-major
    __shared__ float Bs[2][GT_BK][GT_BNP];
    int tid = threadIdx.x;  // 256
    int bm = blockIdx.y * GT_BM;
    int bn = blockIdx.x * GT_BN;
    int wid = tid >> 5;
    int lane = tid & 31;
    int warpM = wid >> 1;  // 0..3
    int warpN = wid & 1;   // 0..1
    int l4 = lane & 3;
    int g = lane >> 2;
    int NT = (K + GT_BK - 1) / GT_BK;

    float acc[2][4][4] = {};  // [mf][nf][reg]

    // async stage of k-tile kt into buffer bf
    auto stage = [&](int kt, int bf) {
        int k0 = kt * GT_BK;
#pragma unroll
        for (int e = tid; e < GT_BM * GT_BK; e += 256) {
            int r = e >> 4, c = e & 15;
            int gm = bm + r, gk = k0 + c;
            bool ok = (gm < M && gk < K);
            uint32_t dst = (uint32_t)__cvta_generic_to_shared(&As[bf][c][r]);
            const float* src = A + ((size_t)(ok ? gm : 0) * K + (ok ? gk : 0));
            cp4(dst, src, ok);
        }
#pragma unroll
        for (int e = tid; e < GT_BN * GT_BK; e += 256) {
            int n, c;
            const float* src;
            bool ok;
            if (TRANSB) {
                n = e >> 4; c = e & 15;
                int gn = bn + n, gk = k0 + c;
                ok = (gn < Nc && gk < K);
                src = Bm + ((size_t)(ok ? gn : 0) * K + (ok ? gk : 0));
            } else {
                c = e >> 6; n = e & 63;
                int gk = k0 + c, gn = bn + n;
                ok = (gk < K && gn < Nc);
                src = Bm + ((size_t)(ok ? gk : 0) * Nc + (ok ? gn : 0));
            }
            uint32_t dst = (uint32_t)__cvta_generic_to_shared(&Bs[bf][c][n]);
            cp4(dst, src, ok);
        }
    };

    stage(0, 0);
    cp_commit();

    for (int kt = 0; kt < NT; kt++) {
        if (kt + 1 < NT) {
            stage(kt + 1, (kt + 1) & 1);
            cp_commit();
            cp_wait<1>();
        } else {
            cp_wait<0>();
        }
        __syncthreads();
        int bf = kt & 1;
#pragma unroll
        for (int kc = 0; kc < 2; kc++) {
            int kb = kc * 8;
            // A fragments: a0=(g,l4) a1=(g+8,l4) a2=(g,l4+4) a3=(g+8,l4+4)
            uint32_t ah[2][4], al[2][4];
#pragma unroll
            for (int mf = 0; mf < 2; mf++) {
                int mb = warpM * 32 + mf * 16;
                float v0 = As[bf][kb + l4][mb + g];
                float v1 = As[bf][kb + l4][mb + g + 8];
                float v2 = As[bf][kb + l4 + 4][mb + g];
                float v3 = As[bf][kb + l4 + 4][mb + g + 8];
                ah[mf][0] = f2tf(v0); ah[mf][1] = f2tf(v1);
                ah[mf][2] = f2tf(v2); ah[mf][3] = f2tf(v3);
                if (PREC == 3) {
                    al[mf][0] = f2tf(v0 - __uint_as_float(ah[mf][0]));
                    al[mf][1] = f2tf(v1 - __uint_as_float(ah[mf][1]));
                    al[mf][2] = f2tf(v2 - __uint_as_float(ah[mf][2]));
                    al[mf][3] = f2tf(v3 - __uint_as_float(ah[mf][3]));
                }
            }
#pragma unroll
            for (int nf = 0; nf < 4; nf++) {
                int nb = warpN * 32 + nf * 8;
                float w0 = Bs[bf][kb + l4][nb + g];
                float w1 = Bs[bf][kb + l4 + 4][nb + g];
                uint32_t bh0 = f2tf(w0), bh1 = f2tf(w1);
                if (PREC == 3) {
                    uint32_t bl0 = f2tf(w0 - __uint_as_float(bh0));
                    uint32_t bl1 = f2tf(w1 - __uint_as_float(bh1));
#pragma unroll
                    for (int mf = 0; mf < 2; mf++) {
                        mma_tf32(acc[mf][nf], al[mf], bh0, bh1);
                        mma_tf32(acc[mf][nf], ah[mf], bl0, bl1);
                        mma_tf32(acc[mf][nf], ah[mf], bh0, bh1);
                    }
                } else {
#pragma unroll
                    for (int mf = 0; mf < 2; mf++)
                        mma_tf32(acc[mf][nf], ah[mf], bh0, bh1);
                }
            }
        }
        __syncthreads();
    }

    // epilogue: c0:(g,2*l4) c1:(g,2*l4+1) c2:(g+8,2*l4) c3:(g+8,2*l4+1)
#pragma unroll
    for (int mf = 0; mf < 2; mf++) {
#pragma unroll
        for (int nf = 0; nf < 4; nf++) {
            int gm0 = bm + warpM * 32 + mf * 16 + g;
            int gn0 = bn + warpN * 32 + nf * 8 + 2 * l4;
#pragma unroll
            for (int hi = 0; hi < 2; hi++) {
                int gm = gm0 + hi * 8;
                if (gm >= M) continue;
#pragma unroll
                for (int jj = 0; jj < 2; jj++) {
                    int gn = gn0 + jj;
                    if (gn >= Nc) continue;
                    float v = acc[mf][nf][hi * 2 + jj] + bias[gn];
                    if (ACT == 1) v = fmaxf(v, 0.f);
                    C[(size_t)gm * Nc + gn] = v;
                }
            }
        }
    }
}

// ---------------- qdot[b,i] = Cin[b,i,:] . wq ----------------
__global__ void qdot_kernel(const float* __restrict__ Cin, const float* __restrict__ wq,
                            float* __restrict__ qdot) {
    int row = blockIdx.x * (blockDim.x / 32) + (threadIdx.x / 32);
    int lane = threadIdx.x & 31;
    if (row >= BN_) return;
    float s = 0.f;
    for (int k = lane; k < Dd; k += 32) s += Cin[(size_t)row * Dd + k] * wq[k];
#pragma unroll
    for (int o = 16; o; o >>= 1) s += __shfl_down_sync(0xffffffffu, s, o);
    if (lane == 0) qdot[row] = s;
}

// ================ persistent per-batch scan (512 threads) ================
#define SCT 512
#define SCAN_SMEM_FLOATS (Nn_ * Dd + 304 + G3P + Nn_ + Nn_ + 32 + 3 * G3P)
#define SCAN_SMEM_BYTES (SCAN_SMEM_FLOATS * 4)

__device__ __forceinline__ float warp_sum(float v) {
#pragma unroll
    for (int o = 16; o; o >>= 1) v += __shfl_down_sync(0xffffffffu, v, o);
    return v;
}
__device__ __forceinline__ float warp_sum_xor(float v) {
#pragma unroll
    for (int o = 16; o; o >>= 1) v += __shfl_xor_sync(0xffffffffu, v, o);
    return v;
}
__device__ __forceinline__ float warp_max_xor(float v) {
#pragma unroll
    for (int o = 16; o; o >>= 1) v = fmaxf(v, __shfl_xor_sync(0xffffffffu, v, o));
    return v;
}

// 512-thread block reduce. ALL threads must call.
__device__ __forceinline__ float block_sum(float v, float* red, int t) {
    int wid = t >> 5, lane = t & 31;
    v = warp_sum(v);
    if (lane == 0) red[wid] = v;
    __syncthreads();
    if (wid == 0) {
        float x = (lane < 16) ? red[lane] : 0.f;
        x = warp_sum(x);
        if (lane == 0) red[16] = x;
    }
    __syncthreads();
    float r = red[16];
    __syncthreads();
    return r;
}

// gi[r] = sum_k Ms[k]*W[k][r] + bias[r]; W fp16 k-major padded to 904.
// 4-way split-K: thread t<452: quarter q=t/113 covers k in [75q,75q+75),
// rowgroup rg=t%113 covers rows [8rg,8rg+8) via one LDG.128 per k.
// ALL 512 threads must call (contains __syncthreads).
__device__ __forceinline__ void matvec_452(const __half* __restrict__ W,
                                           const float* __restrict__ bias,
                                           const float* __restrict__ Ms,
                                           float* __restrict__ gi,
                                           float* __restrict__ part, int t) {
    float a0 = 0.f, a1 = 0.f, a2 = 0.f, a3 = 0.f;
    float a4 = 0.f, a5 = 0.f, a6 = 0.f, a7 = 0.f;
    int q = 0, rg = 0;
    if (t < 452) {
        q = t / 113;
        rg = t - q * 113;
        int k0 = q * 75;
        const uint4* wp = (const uint4*)W;  // 113 uint4 per k-row
#pragma unroll 8
        for (int k = k0; k < k0 + 75; k++) {
            float m = Ms[k];
            uint4 wv = wp[(size_t)k * 113 + rg];
            float2 f0 = __half22float2(*reinterpret_cast<const __half2*>(&wv.x));
            float2 f1 = __half22float2(*reinterpret_cast<const __half2*>(&wv.y));
            float2 f2 = __half22float2(*reinterpret_cast<const __half2*>(&wv.z));
            float2 f3 = __half22float2(*reinterpret_cast<const __half2*>(&wv.w));
            a0 += m * f0.x; a1 += m * f0.y;
            a2 += m * f1.x; a3 += m * f1.y;
            a4 += m * f2.x; a5 += m * f2.y;
            a6 += m * f3.x; a7 += m * f3.y;
        }
    }
    if (t >= 113 && t < 452) {
        float* p = part + (size_t)(q - 1) * G3P + rg * 8;
        p[0] = a0; p[1] = a1; p[2] = a2; p[3] = a3;
        p[4] = a4; p[5] = a5; p[6] = a6; p[7] = a7;
    }
    __syncthreads();
    if (t < 113) {
        int r = t * 8;
        float v[8] = {a0, a1, a2, a3, a4, a5, a6, a7};
#pragma unroll
        for (int j = 0; j < 8; j++) {
            int rr = r + j;
            if (rr < G3)
                gi[rr] = v[j] + part[rr] + part[G3P + rr] + part[2 * G3P + rr] + bias[rr];
        }
    }
    __syncthreads();
}

__global__ void __launch_bounds__(SCT, 1)
scan_layer(const float* __restrict__ Cin, const float* __restrict__ Hin,
           const float* __restrict__ GHp, const float* __restrict__ qdot,
           const float* __restrict__ adj, const __half* __restrict__ Wi,
           const __half* __restrict__ Wh, const float* __restrict__ pbi,
           const float* __restrict__ pbh, const float* __restrict__ wk,
           const float* __restrict__ gbp, float* __restrict__ Pout,
           float* __restrict__ Mall) {
    extern __shared__ float sm[];
    float* Ps = sm;             // 96*300
    float* Ms = Ps + Nn_ * Dd;  // 304
    float* gi = Ms + 304;       // 904
    float* wsm = gi + G3P;      // 96
    float* kap = wsm + Nn_;     // 96
    float* red = kap + Nn_;     // 32
    float* part = red + 32;     // 3*904

    int b = blockIdx.x;
    int t = threadIdx.x;
    float gb = gbp[0];

    // ---- step 0: p0 = GRU(x=0, h=Cin[b,0,:]) ----
    if (t < Dd) Ms[t] = Cin[((size_t)b * Nn_) * Dd + t];
    __syncthreads();
    matvec_452(Wh, pbh, Ms, gi, part, t);  // gh = h @ pwh^T + pbh
    {
        float kp = 0.f;
        if (t < Dd) {
            int d = t;
            float r_ = sigf(pbi[d] + gi[d]);
            float z = sigf(pbi[Dd + d] + gi[Dd + d]);
            float n_ = tanhf(pbi[2 * Dd + d] + r_ * gi[2 * Dd + d]);
            float h = Ms[d];
            float p = (1.f - z) * n_ + z * h;
            Ps[d] = p;
            Pout[((size_t)b * Nn_) * Dd + d] = p;
            Mall[((size_t)b * Nn_) * Dd + d] = 0.f;
            kp = p * wk[d];
        }
        kp = block_sum(kp, red, t);
        if (t == 0) kap[0] = kp;
        __syncthreads();
    }

    // ---- steps 1..95 ----
    for (int i = 1; i < Nn_; i++) {
        // prefetch GRU gmem operands; latency overlaps softmax+M+matvec below.
        float gh0 = 0.f, gh1 = 0.f, gh2 = 0.f, hh = 0.f;
        if (t < Dd) {
            const float* ghrow = GHp + ((size_t)b * Nn_ + i) * G3;
            gh0 = ghrow[t];
            gh1 = ghrow[Dd + t];
            gh2 = ghrow[2 * Dd + t];
            hh = Hin[((size_t)b * Nn_ + i) * Dd + t];
        }

        // attention softmax over j < i: single warp (lane covers j, j+32, j+64)
        if (t < 32) {
            float qd = qdot[b * Nn_ + i];
            const float* arow = adj + ((size_t)b * Nn_ + i) * Nn_;
            float a0 = -1e30f, a1 = -1e30f, a2 = -1e30f;
            int j0 = t, j1 = t + 32, j2 = t + 64;
            if (j0 < i && arow[j0] != 0.f) a0 = qd + kap[j0] + gb;
            if (j1 < i && arow[j1] != 0.f) a1 = qd + kap[j1] + gb;
            if (j2 < i && arow[j2] != 0.f) a2 = qd + kap[j2] + gb;
            float mx = warp_max_xor(fmaxf(a0, fmaxf(a1, a2)));
            float e0 = (a0 > -1e29f) ? __expf(a0 - mx) : 0.f;
            float e1 = (a1 > -1e29f) ? __expf(a1 - mx) : 0.f;
            float e2 = (a2 > -1e29f) ? __expf(a2 - mx) : 0.f;
            float s = warp_sum_xor(e0 + e1 + e2);
            float inv = 1.f / s;
            wsm[j0] = e0 * inv;
            wsm[j1] = e1 * inv;
            wsm[j2] = e2 * inv;
        }
        __syncthreads();

        // M = sum_j w_j * P_j (SMEM P, dual accumulator halves the FMA chain)
        if (t < Dd) {
            int d = t;
            float m0 = 0.f, m1 = 0.f;
            int j = 0;
            for (; j + 1 < i; j += 2) {
                m0 += wsm[j] * Ps[j * Dd + d];
                m1 += wsm[j + 1] * Ps[(j + 1) * Dd + d];
            }
            if (j < i) m0 += wsm[j] * Ps[j * Dd + d];
            float m = m0 + m1;
            Ms[d] = m;
            Mall[((size_t)b * Nn_ + i) * Dd + d] = m;
        }
        __syncthreads();

        // gi = M @ pwi^T + pbi (fp16 4-way split-K matvec)
        matvec_452(Wi, pbi, Ms, gi, part, t);

        // p_i = GRU(gi, prefetched rows); write P; kappa_i
        {
            float kp = 0.f;
            if (t < Dd) {
                int d = t;
                float r_ = sigf(gi[d] + gh0);
                float z = sigf(gi[Dd + d] + gh1);
                float n_ = tanhf(gi[2 * Dd + d] + r_ * gh2);
                float p = (1.f - z) * n_ + z * hh;
                Ps[i * Dd + d] = p;
                Pout[((size_t)b * Nn_ + i) * Dd + d] = p;
                kp = p * wk[d];
            }
            kp = block_sum(kp, red, t);
            if (t == 0) kap[i] = kp;
            __syncthreads();
        }
    }
}

// ---------------- deferred c combine: CL = GRU(GIc, GHc, h=Mall) ----------------
__global__ void combine_c(const float* __restrict__ GIc, const float* __restrict__ GHc,
                          const float* __restrict__ Mall, float* __restrict__ CL) {
    int idx = blockIdx.x * blockDim.x + threadIdx.x;
    if (idx >= BN_ * Dd) return;
    int row = idx / Dd, d = idx % Dd;
    const float* gi = GIc + (size_t)row * G3;
    const float* gh = GHc + (size_t)row * G3;
    float r_ = sigf(gi[d] + gh[d]);
    float z = sigf(gi[Dd + d] + gh[Dd + d]);
    float n_ = tanhf(gi[2 * Dd + d] + r_ * gh[2 * Dd + d]);
    float h = Mall[idx];
    CL[idx] = (1.f - z) * n_ + z * h;
}

// ---------------- fused concat: Hcat = [seg0..seg8 (300 each), features (1024)] ----
__global__ void concat_all(const float* __restrict__ s0, const float* __restrict__ s1,
                           const float* __restrict__ s2, const float* __restrict__ s3,
                           const float* __restrict__ s4, const float* __restrict__ s5,
                           const float* __restrict__ s6, const float* __restrict__ s7,
                           const float* __restrict__ s8, const float* __restrict__ feat,
                           float* __restrict__ dst) {
    size_t idx = (size_t)blockIdx.x * blockDim.x + threadIdx.x;
    if (idx >= (size_t)BN_ * IN_DIM) return;
    int row = (int)(idx / IN_DIM);
    int c = (int)(idx % IN_DIM);
    float v;
    if (c < 9 * Dd) {
        int s = c / Dd, d = c % Dd;
        const float* segs[9] = {s0, s1, s2, s3, s4, s5, s6, s7, s8};
        v = segs[s][(size_t)row * Dd + d];
    } else {
        v = feat[(size_t)row * Ee + (c - 9 * Dd)];
    }
    dst[idx] = v;
}

// ---------------- launch ----------------
extern "C" void kernel_launch(void* const* d_in, const int* in_sizes, int n_in,
                              void* d_out, int out_size) {
    const float* features = (const float*)d_in[0];
    const float* adj = (const float*)d_in[1];
    const float* fc1_w = (const float*)d_in[3];
    const float* fc1_b = (const float*)d_in[4];
    const float* gc_wih = (const float*)d_in[5];
    const float* gc_whh = (const float*)d_in[6];
    const float* gc_bih = (const float*)d_in[7];
    const float* gc_bhh = (const float*)d_in[8];
    const float* gp_wih = (const float*)d_in[9];
    const float* gp_whh = (const float*)d_in[10];
    const float* gp_bih = (const float*)d_in[11];
    const float* gp_bhh = (const float*)d_in[12];
    const float* gat_wq = (const float*)d_in[13];
    const float* gat_wk = (const float*)d_in[14];
    const float* gat_b = (const float*)d_in[15];
    const float* mlp_w0 = (const float*)d_in[16];
    const float* mlp_b0 = (const float*)d_in[17];
    const float* mlp_w1 = (const float*)d_in[18];
    const float* mlp_b1 = (const float*)d_in[19];
    const float* mlp_w2 = (const float*)d_in[20];
    const float* mlp_b2 = (const float*)d_in[21];
    float* out = (float*)d_out;

    float *H0, *CLb, *Pb, *GIc, *GHp, *GHc, *Mall, *qdot, *Hcat, *x1, *x2;
    __half *pwiTh, *pwhTh;
    cudaGetSymbolAddress((void**)&H0, d_H0);
    cudaGetSymbolAddress((void**)&CLb, d_CL);
    cudaGetSymbolAddress((void**)&Pb, d_Pl);
    cudaGetSymbolAddress((void**)&GIc, d_GIc);
    cudaGetSymbolAddress((void**)&GHp, d_GHp);
    cudaGetSymbolAddress((void**)&GHc, d_GHc);
    cudaGetSymbolAddress((void**)&Mall, d_Mall);
    cudaGetSymbolAddress((void**)&qdot, d_qdot);
    cudaGetSymbolAddress((void**)&pwiTh, d_pwiTh);
    cudaGetSymbolAddress((void**)&pwhTh, d_pwhTh);
    cudaGetSymbolAddress((void**)&Hcat, d_Hcat);
    cudaGetSymbolAddress((void**)&x1, d_x1);
    cudaGetSymbolAddress((void**)&x2, d_x2);

    cudaFuncSetAttribute(scan_layer, cudaFuncAttributeMaxDynamicSharedMemorySize,
                         SCAN_SMEM_BYTES);

    // transpose+convert+pad p-GRU weights (inside graph; deterministic)
    {
        int tot = Ll * Dd * G3P;
        transpose_weights<<<(tot + 255) / 256, 256>>>(gp_wih, gp_whh, pwiTh, pwhTh);
    }

    // H0 = relu(features @ fc1_w + fc1_b)  — single-pass tf32 (gate-contracted)
    {
        dim3 g((Dd + GT_BN - 1) / GT_BN, (BN_ + GT_BM - 1) / GT_BM);
        gemm_tc<false, 1, 1><<<g, 256>>>(features, fc1_w, fc1_b, H0, BN_, Dd, Ee);
    }

    float* CL_l[Ll];
    float* P_l[Ll];
    for (int l = 0; l < Ll; l++) {
        CL_l[l] = CLb + (size_t)l * BN_ * Dd;
        P_l[l] = Pb + (size_t)l * BN_ * Dd;
    }
    const float* Cin_l[Ll] = {H0, CL_l[0], CL_l[1], CL_l[2]};

    dim3 g900((G3 + GT_BN - 1) / GT_BN, (BN_ + GT_BM - 1) / GT_BM);
    for (int l = 0; l < Ll; l++) {
        const float* Cin = Cin_l[l];
        const float* Hin = (l == 0) ? H0 : (l == 1) ? CL_l[0] : (l == 2) ? P_l[0] : CL_l[1];
        const float* cwi = gc_wih + (size_t)l * G3 * Dd;
        const float* cwh = gc_whh + (size_t)l * G3 * Dd;
        const float* cbi = gc_bih + (size_t)l * G3;
        const float* cbh = gc_bhh + (size_t)l * G3;
        const float* pwh = gp_whh + (size_t)l * G3 * Dd;
        const float* pbi = gp_bih + (size_t)l * G3;
        const float* pbh = gp_bhh + (size_t)l * G3;
        const float* wq = gat_wq + (size_t)l * Dd;
        const float* wk = gat_wk + (size_t)l * Dd;
        const float* gb = gat_b + l;
        const __half* Wi = pwiTh + (size_t)l * Dd * G3P;
        const __half* Wh = pwhTh + (size_t)l * Dd * G3P;

        // batched precomputes — single-pass tf32 (errors contracted by GRU gates)
        gemm_tc<true, 0, 1><<<g900, 256>>>(Cin, cwi, cbi, GIc, BN_, G3, Dd);
        gemm_tc<true, 0, 1><<<g900, 256>>>(Hin, pwh, pbh, GHp, BN_, G3, Dd);
        qdot_kernel<<<(BN_ + 7) / 8, 256>>>(Cin, wq, qdot);

        // whole 96-step recurrence: one persistent kernel, one block per batch
        scan_layer<<<Bb, SCT, SCAN_SMEM_BYTES>>>(Cin, Hin, GHp, qdot, adj, Wi, Wh,
                                                 pbi, pbh, wk, gb, P_l[l], Mall);

        // deferred c-GRU
        gemm_tc<true, 0, 1><<<g900, 256>>>(Mall, cwh, cbh, GHc, BN_, G3, Dd);
        combine_c<<<(BN_ * Dd + 255) / 256, 256>>>(GIc, GHc, Mall, CL_l[l]);
    }

    // fused concat: [H0, CL0, P0, CL1, P1, CL2, P2, CL3, P3, features]
    {
        size_t tot = (size_t)BN_ * IN_DIM;
        int nb = (int)((tot + 255) / 256);
        concat_all<<<nb, 256>>>(H0, CL_l[0], P_l[0], CL_l[1], P_l[1], CL_l[2],
                                P_l[2], CL_l[3], P_l[3], features, Hcat);
    }

    // MLP — output path keeps 3xTF32 (fp32-class accuracy)
    {
        dim3 g0((Dd + GT_BN - 1) / GT_BN, (BN_ + GT_BM - 1) / GT_BM);
        gemm_tc<false, 1, 3><<<g0, 256>>>(Hcat, mlp_w0, mlp_b0, x1, BN_, Dd, IN_DIM);
        gemm_tc<false, 1, 3><<<g0, 256>>>(x1, mlp_w1, mlp_b1, x2, BN_, Dd, Dd);
        dim3 g2((NCc + GT_BN - 1) / GT_BN, (BN_ + GT_BM - 1) / GT_BM);
        gemm_tc<false, 0, 3><<<g2, 256>>>(x2, mlp_w2, mlp_b2, out, BN_, NCc, Dd);
    }
}